// round 15
// baseline (speedup 1.0000x reference)
#include <cuda_runtime.h>
#include <cuda_bf16.h>
#include <math.h>
#include <stdint.h>

// Problem constants
#define Bb 16
#define Tt 16
#define Cc 64
#define HD 64
#define HW 1024
#define IMW 32

// Scratch (device globals: no allocation allowed)
__device__ float g_h   [Bb*HD*HW];
__device__ float g_hode[Bb*HD*HW];
__device__ float g_rh  [Bb*HD*HW];
__device__ float g_u   [Bb*HD*HW];
__device__ float g_gx  [(size_t)Tt*Bb*2*HD*HW];   // x-part of gates conv (+bias)
__device__ float g_cx  [(size_t)Tt*Bb*HD*HW];     // x-part of cand conv (+bias)
// Pre-split weights, bf16 bits: [hl][row][k], k = tap*64 + ci
// rows: 0 ode | 64 gates_h(128) | 192 cand_h | 256 gates_x(128) | 384 cand_x
__device__ __align__(16) unsigned short g_Bw[2][448][576];

// Smem (halves): slab 108 rc-rows (3x36) x stride 72; B NOC rows x stride 72
#define SLAB_STR 72
#define SLAB_RC  108
#define SLABH    (SLAB_RC*SLAB_STR)   // 7776
#define BSTR     72

// bf16 m16n8k16 MMA (standard PTX, sm_80+)
__device__ __forceinline__ void mma16816(float* c, const unsigned* a,
                                         unsigned b0, unsigned b1) {
    asm volatile(
        "mma.sync.aligned.m16n8k16.row.col.f32.bf16.bf16.f32 "
        "{%0,%1,%2,%3}, {%4,%5,%6,%7}, {%8,%9}, {%0,%1,%2,%3};\n"
        : "+f"(c[0]), "+f"(c[1]), "+f"(c[2]), "+f"(c[3])
        : "r"(a[0]), "r"(a[1]), "r"(a[2]), "r"(a[3]), "r"(b0), "r"(b1));
}
__device__ __forceinline__ void ldsm_x4(unsigned* r, uint32_t addr) {
    asm volatile("ldmatrix.sync.aligned.m8n8.x4.shared.b16 {%0,%1,%2,%3}, [%4];"
        : "=r"(r[0]), "=r"(r[1]), "=r"(r[2]), "=r"(r[3]) : "r"(addr));
}
__device__ __forceinline__ float sigmoidf_(float x) { return 1.f / (1.f + expf(-x)); }

// ===========================================================================
// Weight pre-split: fp32 -> bf16 hi/lo, layout [hl][row][tap*64+ci]
// ===========================================================================
__global__ void k_wsplit(const float* __restrict__ w_ode,
                         const float* __restrict__ w_gates,
                         const float* __restrict__ w_can)
{
    int idx = blockIdx.x*256 + threadIdx.x;     // 448*576 = 258048
    if (idx >= 448*576) return;
    int r = idx / 576, k = idx % 576;
    int tap = k >> 6, ci = k & 63;

    float v;
    if      (r < 64)  v = w_ode  [ r       *576  + ci*9      + tap];
    else if (r < 192) v = w_gates[(r-64)   *1152 + (64+ci)*9 + tap];
    else if (r < 256) v = w_can  [(r-192)  *1152 + (64+ci)*9 + tap];
    else if (r < 384) v = w_gates[(r-256)  *1152 + ci*9      + tap];
    else              v = w_can  [(r-384)  *1152 + ci*9      + tap];

    __nv_bfloat16 h = __float2bfloat16_rn(v);
    __nv_bfloat16 l = __float2bfloat16_rn(v - __bfloat162float(h));
    g_Bw[0][r][k] = __bfloat16_as_ushort(h);
    g_Bw[1][r][k] = __bfloat16_as_ushort(l);
}

// ===========================================================================
// Conv-as-GEMM, single pass, wide N, register-prefetched B everywhere.
// CTA (256 thr, 8 warps) owns one image row (32 px) x NOC oc.
// Warp: mt=w>>2 (16px half), nq=w&3 (NOC/4 oc block).
// MODE: 0=ODE(N64) 1=GATES(N128: reset|update) 2=CAND(N64) 3=PRE_G(N128)
//       4=PRE_C(N64).  grid = (32 rows, nimg).
// ===========================================================================
template<int MODE>
__global__ void __launch_bounds__(256) k_conv(
    const float* __restrict__ x0, const float* __restrict__ ts,
    const float* __restrict__ mask, const float* __restrict__ b_ode,
    const float* __restrict__ b_gates, const float* __restrict__ b_can,
    int step)
{
    constexpr int NOC    = (MODE == 1 || MODE == 3) ? 128 : 64;
    constexpr int NTILES = NOC/32;      // n8-tiles per warp (2 or 4)
    constexpr int NSLOT  = NOC/32;      // B prefetch slots per thread (2 or 4)

    extern __shared__ unsigned short sm2[];
    unsigned short* slab_hi = sm2;
    unsigned short* slab_lo = sm2 + SLABH;
    unsigned short* Bs_hi   = sm2 + 2*SLABH;
    unsigned short* Bs_lo   = sm2 + 2*SLABH + NOC*BSTR;

    const int tid  = threadIdx.x;
    const int w    = tid >> 5, lane = tid & 31;
    const int mt   = w >> 2, nq = w & 3;
    const int tile = blockIdx.x;        // image row
    const int img  = blockIdx.y;

    const float* in;
    if (MODE >= 3) {
        int t = img >> 4, b = img & 15;
        in = x0 + ((size_t)(b*Tt + (Tt-1-t))*Cc)*HW;
    } else {
        in = (MODE == 0 ? g_h : (MODE == 1 ? g_hode : g_rh)) + (size_t)img*HD*HW;
    }
    const int rowoff = (MODE == 0) ? 0
                     : (MODE == 1) ? 64
                     : (MODE == 2) ? 192
                     : (MODE == 3) ? 256
                     : 384;

    // ---- Build slabs: image rows tile-1 .. tile+1, cols -1..34 ----
    for (int i = tid; i < SLAB_RC*64; i += 256) {
        int ci = i / SLAB_RC, rc = i - ci*SLAB_RC;
        int rr = rc / 36, cc = rc - rr*36;
        int ir = tile + rr - 1, ic = cc - 1;
        float v = 0.f;
        if ((unsigned)ir < 32u && (unsigned)ic < 32u)
            v = in[ci*HW + ir*IMW + ic];
        __nv_bfloat16 h = __float2bfloat16_rn(v);
        __nv_bfloat16 l = __float2bfloat16_rn(v - __bfloat162float(h));
        slab_hi[rc*SLAB_STR + ci] = __bfloat16_as_ushort(h);
        slab_lo[rc*SLAB_STR + ci] = __bfloat16_as_ushort(l);
    }

    const uint32_t slab_hi_u = (uint32_t)__cvta_generic_to_shared(slab_hi);
    const uint32_t slab_lo_u = (uint32_t)__cvta_generic_to_shared(slab_lo);
    const uint32_t bs_hi_u   = (uint32_t)__cvta_generic_to_shared(Bs_hi);
    const uint32_t bs_lo_u   = (uint32_t)__cvta_generic_to_shared(Bs_lo);

    float acc[NTILES][4];
    #pragma unroll
    for (int nt = 0; nt < NTILES; nt++)
        #pragma unroll
        for (int e = 0; e < 4; e++) acc[nt][e] = 0.f;

    // B fragment smem byte offset (warp's oc block = nq*(NOC/4))
    const uint32_t bfrag0 = (uint32_t)((nq*(NOC/4) + (lane & 7) + ((lane >> 4) << 3))*BSTR*2)
                          + (((lane >> 3) & 1) << 4);

    // B register prefetch: thread covers NSLOT (row, 16B-chunk) slots
    uint4 rh[NSLOT], rl[NSLOT];
    #pragma unroll
    for (int s = 0; s < NSLOT; s++) {
        const int i = tid + s*256, row = i >> 3, q = i & 7;
        rh[s] = *(reinterpret_cast<const uint4*>(&g_Bw[0][rowoff + row][0]) + q);
        rl[s] = *(reinterpret_cast<const uint4*>(&g_Bw[1][rowoff + row][0]) + q);
    }

    float dt = 0.f, m = 0.f;
    if (MODE == 0) dt = (step == 0) ? -0.01f : (ts[Tt-1-step] - ts[Tt-step]);
    if (MODE == 2) m  = mask[img*Tt + (Tt-1-step)];

    #pragma unroll 1
    for (int tap = 0; tap < 9; tap++) {
        __syncthreads();   // prior-tap B reads done (tap0: slab stores issued)
        #pragma unroll
        for (int s = 0; s < NSLOT; s++) {
            const int i = tid + s*256, row = i >> 3, q = i & 7;
            *reinterpret_cast<uint4*>(reinterpret_cast<char*>(Bs_hi) + row*(BSTR*2) + q*16) = rh[s];
            *reinterpret_cast<uint4*>(reinterpret_cast<char*>(Bs_lo) + row*(BSTR*2) + q*16) = rl[s];
        }
        __syncthreads();
        if (tap < 8) {
            const int t1 = (tap + 1)*64;
            #pragma unroll
            for (int s = 0; s < NSLOT; s++) {
                const int i = tid + s*256, row = i >> 3, q = i & 7;
                rh[s] = *(reinterpret_cast<const uint4*>(&g_Bw[0][rowoff + row][t1]) + q);
                rl[s] = *(reinterpret_cast<const uint4*>(&g_Bw[1][rowoff + row][t1]) + q);
            }
        }

        const int tr = tap/3, tc = tap - tr*3;
        const int base_rc = tr*36 + tc + mt*16;
        const uint32_t a_off = (uint32_t)((base_rc + (lane & 15))*SLAB_STR*2)
                             + ((lane >> 4) << 4);

        #pragma unroll
        for (int kq = 0; kq < 4; kq++) {
            unsigned ah[4], al[4];
            ldsm_x4(ah, slab_hi_u + a_off + kq*32);
            ldsm_x4(al, slab_lo_u + a_off + kq*32);
            #pragma unroll
            for (int p = 0; p < NTILES/2; p++) {
                unsigned bh[4], bl[4];
                const uint32_t boff = bfrag0 + (uint32_t)(p*16*BSTR*2) + kq*32;
                ldsm_x4(bh, bs_hi_u + boff);
                mma16816(acc[2*p],   ah, bh[0], bh[1]);
                mma16816(acc[2*p+1], ah, bh[2], bh[3]);
                mma16816(acc[2*p],   al, bh[0], bh[1]);
                mma16816(acc[2*p+1], al, bh[2], bh[3]);
                ldsm_x4(bl, bs_lo_u + boff);
                mma16816(acc[2*p],   ah, bl[0], bl[1]);
                mma16816(acc[2*p+1], ah, bl[2], bl[3]);
            }
        }
    }

    // ---- Epilogue: thread owns 4*NTILES (px, oc) values ----
    #pragma unroll
    for (int nt = 0; nt < NTILES; nt++) {
        #pragma unroll
        for (int e = 0; e < 4; e++) {
            const int c  = mt*16 + (lane >> 2) + (e >> 1)*8;
            const int oc = nq*(NOC/4) + nt*8 + (lane & 3)*2 + (e & 1);
            const int px = tile*IMW + c;
            float v = acc[nt][e];
            if (MODE == 0) {
                size_t ib = (size_t)img*HD*HW + (size_t)oc*HW + px;
                g_hode[ib] = g_h[ib] + tanhf(v + b_ode[oc])*dt;
            } else if (MODE == 1) {
                float gx = g_gx[((size_t)(step*Bb + img)*(2*HD) + oc)*HW + px];
                float g = sigmoidf_(v + gx);
                size_t ib = (size_t)img*HD*HW + (size_t)(oc & 63)*HW + px;
                if (oc < 64) g_rh[ib] = g * g_hode[ib];
                else         g_u[ib]  = g;
            } else if (MODE == 2) {
                float cx = g_cx[((size_t)(step*Bb + img)*HD + oc)*HW + px];
                size_t ib = (size_t)img*HD*HW + (size_t)oc*HW + px;
                float ho = g_hode[ib];
                g_h[ib] = ho + m*g_u[ib]*(tanhf(v + cx) - ho);
            } else if (MODE == 3) {
                g_gx[((size_t)img*(2*HD) + oc)*HW + px] = v + b_gates[oc];
            } else {
                g_cx[((size_t)img*HD + oc)*HW + px] = v + b_can[oc];
            }
        }
    }
}

// ===========================================================================
// Head: z1 = relu(W1 h + b1); z2 = W2 z1 + b2; out = [z2[:64] ; |z2[64:]|]
// ===========================================================================
__global__ void __launch_bounds__(256) k_final(
    const float* __restrict__ w1, const float* __restrict__ b1,
    const float* __restrict__ w2, const float* __restrict__ b2,
    float* __restrict__ out)
{
    extern __shared__ float smemf[];
    float* w1s = smemf;          // [64][64]
    float* w2s = smemf + 4096;   // [128][64]
    const int tid = threadIdx.x, pb = blockIdx.x, b = blockIdx.y;
    for (int i = tid; i < 4096; i += 256) w1s[i] = w1[i];
    for (int i = tid; i < 8192; i += 256) w2s[i] = w2[i];
    __syncthreads();

    const int pix = pb*256 + tid;
    float z1[64];
    #pragma unroll
    for (int co = 0; co < 64; co++) z1[co] = b1[co];
    for (int ci = 0; ci < 64; ci++) {
        float hv = g_h[((size_t)b*HD + ci)*HW + pix];
        #pragma unroll
        for (int co = 0; co < 64; co++) z1[co] += w1s[co*64 + ci]*hv;
    }
    #pragma unroll
    for (int co = 0; co < 64; co++) z1[co] = fmaxf(z1[co], 0.f);

    for (int co2 = 0; co2 < 128; co2++) {
        float a = b2[co2];
        #pragma unroll
        for (int ci = 0; ci < 64; ci++) a += w2s[co2*64 + ci]*z1[ci];
        if (co2 < 64)
            out[((size_t)b*HD + co2)*HW + pix] = a;
        else
            out[(size_t)Bb*HD*HW + ((size_t)b*HD + (co2 - 64))*HW + pix] = fabsf(a);
    }
}

// ---------------------------------------------------------------------------
extern "C" void kernel_launch(void* const* d_in, const int* in_sizes, int n_in,
                              void* d_out, int out_size)
{
    const float* input   = (const float*)d_in[0];
    const float* ts      = (const float*)d_in[1];
    const float* mask    = (const float*)d_in[2];
    const float* w_gates = (const float*)d_in[3];
    const float* b_gates = (const float*)d_in[4];
    const float* w_can   = (const float*)d_in[5];
    const float* b_can   = (const float*)d_in[6];
    const float* w_ode   = (const float*)d_in[7];
    const float* b_ode   = (const float*)d_in[8];
    const float* w_t1    = (const float*)d_in[9];
    const float* b_t1    = (const float*)d_in[10];
    const float* w_t2    = (const float*)d_in[11];
    const float* b_t2    = (const float*)d_in[12];
    float* out = (float*)d_out;

    float* hptr;
    cudaGetSymbolAddress((void**)&hptr, g_h);

    const int SMEM64  = (2*SLABH + 2*64*BSTR)  * 2;   // 49536 B
    const int SMEM128 = (2*SLABH + 2*128*BSTR) * 2;   // 67968 B

    cudaFuncSetAttribute(k_conv<0>, cudaFuncAttributeMaxDynamicSharedMemorySize, SMEM64);
    cudaFuncSetAttribute(k_conv<1>, cudaFuncAttributeMaxDynamicSharedMemorySize, SMEM128);
    cudaFuncSetAttribute(k_conv<2>, cudaFuncAttributeMaxDynamicSharedMemorySize, SMEM64);
    cudaFuncSetAttribute(k_conv<3>, cudaFuncAttributeMaxDynamicSharedMemorySize, SMEM128);
    cudaFuncSetAttribute(k_conv<4>, cudaFuncAttributeMaxDynamicSharedMemorySize, SMEM64);

    cudaMemsetAsync(hptr, 0, (size_t)Bb*HD*HW*sizeof(float));
    k_wsplit<<<1008, 256>>>(w_ode, w_gates, w_can);

    // Precompute x-contributions for all T steps
    k_conv<3><<<dim3(32, Tt*Bb), 256, SMEM128>>>(input, ts, mask, b_ode, b_gates, b_can, 0);
    k_conv<4><<<dim3(32, Tt*Bb), 256, SMEM64 >>>(input, ts, mask, b_ode, b_gates, b_can, 0);

    // Sequential scan
    for (int s = 0; s < Tt; s++) {
        k_conv<0><<<dim3(32, Bb), 256, SMEM64 >>>(input, ts, mask, b_ode, b_gates, b_can, s);
        k_conv<1><<<dim3(32, Bb), 256, SMEM128>>>(input, ts, mask, b_ode, b_gates, b_can, s);
        k_conv<2><<<dim3(32, Bb), 256, SMEM64 >>>(input, ts, mask, b_ode, b_gates, b_can, s);
    }

    k_final<<<dim3(4, Bb), 256, 12288*(int)sizeof(float)>>>(w_t1, b_t1, w_t2, b_t2, out);
}

// round 16
// speedup vs baseline: 1.1382x; 1.1382x over previous
#include <cuda_runtime.h>
#include <cuda_bf16.h>
#include <math.h>
#include <stdint.h>

// Problem constants
#define Bb 16
#define Tt 16
#define Cc 64
#define HD 64
#define HW 1024
#define IMW 32

// Scratch (device globals: no allocation allowed)
__device__ float g_h   [Bb*HD*HW];
__device__ float g_hode[Bb*HD*HW];
__device__ float g_rh  [Bb*HD*HW];
__device__ float g_u   [Bb*HD*HW];
__device__ float g_gx  [(size_t)Tt*Bb*2*HD*HW];   // x-part of gates conv (+bias)
__device__ float g_cx  [(size_t)Tt*Bb*HD*HW];     // x-part of cand conv (+bias)
// Pre-split weights, bf16 bits: [hl][row][k], k = tap*64 + ci
// rows: 0 ode | 64 gates_h(128) | 192 cand_h | 256 gates_x(128) | 384 cand_x
__device__ __align__(16) unsigned short g_Bw[2][448][576];

// Smem (halves): slab 108 rc-rows (3x36) x stride 72; B 64 rows x stride 72
#define SLAB_STR 72
#define SLAB_RC  108
#define SLABH    (SLAB_RC*SLAB_STR)   // 7776
#define BSTR     72
#define BH       (64*BSTR)            // 4608
#define SMEMB    ((2*SLABH + 2*BH)*2) // 49536 bytes

// bf16 m16n8k16 MMA (standard PTX, sm_80+)
__device__ __forceinline__ void mma16816(float* c, const unsigned* a,
                                         unsigned b0, unsigned b1) {
    asm volatile(
        "mma.sync.aligned.m16n8k16.row.col.f32.bf16.bf16.f32 "
        "{%0,%1,%2,%3}, {%4,%5,%6,%7}, {%8,%9}, {%0,%1,%2,%3};\n"
        : "+f"(c[0]), "+f"(c[1]), "+f"(c[2]), "+f"(c[3])
        : "r"(a[0]), "r"(a[1]), "r"(a[2]), "r"(a[3]), "r"(b0), "r"(b1));
}
__device__ __forceinline__ void ldsm_x4(unsigned* r, uint32_t addr) {
    asm volatile("ldmatrix.sync.aligned.m8n8.x4.shared.b16 {%0,%1,%2,%3}, [%4];"
        : "=r"(r[0]), "=r"(r[1]), "=r"(r[2]), "=r"(r[3]) : "r"(addr));
}
__device__ __forceinline__ float sigmoidf_(float x) { return 1.f / (1.f + expf(-x)); }

// ===========================================================================
// Weight pre-split: fp32 -> bf16 hi/lo, layout [hl][row][tap*64+ci]
// ===========================================================================
__global__ void k_wsplit(const float* __restrict__ w_ode,
                         const float* __restrict__ w_gates,
                         const float* __restrict__ w_can)
{
    int idx = blockIdx.x*256 + threadIdx.x;     // 448*576 = 258048
    if (idx >= 448*576) return;
    int r = idx / 576, k = idx % 576;
    int tap = k >> 6, ci = k & 63;

    float v;
    if      (r < 64)  v = w_ode  [ r       *576  + ci*9      + tap];
    else if (r < 192) v = w_gates[(r-64)   *1152 + (64+ci)*9 + tap];
    else if (r < 256) v = w_can  [(r-192)  *1152 + (64+ci)*9 + tap];
    else if (r < 384) v = w_gates[(r-256)  *1152 + ci*9      + tap];
    else              v = w_can  [(r-384)  *1152 + ci*9      + tap];

    __nv_bfloat16 h = __float2bfloat16_rn(v);
    __nv_bfloat16 l = __float2bfloat16_rn(v - __bfloat162float(h));
    g_Bw[0][r][k] = __bfloat16_as_ushort(h);
    g_Bw[1][r][k] = __bfloat16_as_ushort(l);
}

// ===========================================================================
// Conv-as-GEMM with UNIT FUSION (R13 config). CTA (256 thr, 8 warps) owns one
// image row (32 px) and runs NU sequential [32px x 64oc] conv-units over the
// SAME slab. MODE: 0=ODE(1u) 1=GATES(2u) 2=CAND(1u) 3=PRE(3u: gx0,gx1,cx)
// grid = (32 rows, nimg). Warp w: mt=w>>2 (16px half), nq=w&3 (16oc quarter).
// Slab build packs 2 adjacent ci per 32-bit store (bf16x2).
// ===========================================================================
template<int MODE>
__global__ void __launch_bounds__(256) k_conv(
    const float* __restrict__ x0, const float* __restrict__ ts,
    const float* __restrict__ mask, const float* __restrict__ b_ode,
    const float* __restrict__ b_gates, const float* __restrict__ b_can,
    int step)
{
    constexpr int NU = (MODE == 1) ? 2 : (MODE == 3) ? 3 : 1;

    extern __shared__ unsigned short sm2[];
    unsigned short* slab_hi = sm2;
    unsigned short* slab_lo = sm2 + SLABH;
    unsigned short* Bs_hi   = sm2 + 2*SLABH;
    unsigned short* Bs_lo   = sm2 + 2*SLABH + BH;

    const int tid  = threadIdx.x;
    const int w    = tid >> 5, lane = tid & 31;
    const int mt   = w >> 2, nq = w & 3;
    const int tile = blockIdx.x;        // image row
    const int img  = blockIdx.y;

    const float* in;
    if (MODE == 3) {
        int t = img >> 4, b = img & 15;
        in = x0 + ((size_t)(b*Tt + (Tt-1-t))*Cc)*HW;
    } else {
        in = (MODE == 0 ? g_h : (MODE == 1 ? g_hode : g_rh)) + (size_t)img*HD*HW;
    }

    auto ROWOFF = [](int u) {
        return (MODE == 0) ? 0
             : (MODE == 1) ? 64 + u*64
             : (MODE == 2) ? 192
             : (u == 2 ? 384 : 256 + u*64);
    };

    // ---- Build slabs (2 ci per 4B store): rows tile-1..tile+1, cols -1..34 ----
    for (int i = tid; i < 32*SLAB_RC; i += 256) {
        const int c2 = i / SLAB_RC;            // ci pair index (ci = 2c2, 2c2+1)
        const int rc = i - c2*SLAB_RC;
        const int rr = rc / 36, cc = rc - rr*36;
        const int ir = tile + rr - 1, ic = cc - 1;
        float va = 0.f, vb = 0.f;
        if ((unsigned)ir < 32u && (unsigned)ic < 32u) {
            const float* p = in + (2*c2)*HW + ir*IMW + ic;
            va = p[0];
            vb = p[HW];
        }
        __nv_bfloat162 h2 = __floats2bfloat162_rn(va, vb);
        __nv_bfloat162 l2 = __floats2bfloat162_rn(va - __bfloat162float(h2.x),
                                                  vb - __bfloat162float(h2.y));
        *reinterpret_cast<__nv_bfloat162*>(&slab_hi[rc*SLAB_STR + 2*c2]) = h2;
        *reinterpret_cast<__nv_bfloat162*>(&slab_lo[rc*SLAB_STR + 2*c2]) = l2;
    }

    const uint32_t slab_hi_u = (uint32_t)__cvta_generic_to_shared(slab_hi);
    const uint32_t slab_lo_u = (uint32_t)__cvta_generic_to_shared(slab_lo);
    const uint32_t bs_hi_u   = (uint32_t)__cvta_generic_to_shared(Bs_hi);
    const uint32_t bs_lo_u   = (uint32_t)__cvta_generic_to_shared(Bs_lo);

    // B fragment smem byte offset (16 oc rows for this warp's quarter)
    const uint32_t bfrag0 = (uint32_t)((nq*16 + (lane & 7) + ((lane >> 4) << 3))*BSTR*2)
                          + (((lane >> 3) & 1) << 4);

    // B register prefetch: thread covers rows n = tid>>3 and (tid+256)>>3
    const int bn0 = tid >> 3,         bq0 = tid & 7;
    const int bn1 = (tid + 256) >> 3, bq1 = tid & 7;
    uint4 rh[2], rl[2];
    rh[0] = *(reinterpret_cast<const uint4*>(&g_Bw[0][ROWOFF(0) + bn0][0]) + bq0);
    rl[0] = *(reinterpret_cast<const uint4*>(&g_Bw[1][ROWOFF(0) + bn0][0]) + bq0);
    rh[1] = *(reinterpret_cast<const uint4*>(&g_Bw[0][ROWOFF(0) + bn1][0]) + bq1);
    rl[1] = *(reinterpret_cast<const uint4*>(&g_Bw[1][ROWOFF(0) + bn1][0]) + bq1);

    float dt = 0.f, m = 0.f;
    if (MODE == 0) dt = (step == 0) ? -0.01f : (ts[Tt-1-step] - ts[Tt-step]);
    if (MODE == 2) m  = mask[img*Tt + (Tt-1-step)];

    #pragma unroll
    for (int u = 0; u < NU; u++) {
        float acc[2][4];
        #pragma unroll
        for (int nt = 0; nt < 2; nt++)
            #pragma unroll
            for (int e = 0; e < 4; e++) acc[nt][e] = 0.f;

        #pragma unroll 1
        for (int tap = 0; tap < 9; tap++) {
            __syncthreads();   // prior reads of Bs done (tap0/u0: slab stores issued)
            *reinterpret_cast<uint4*>(reinterpret_cast<char*>(Bs_hi) + bn0*(BSTR*2) + bq0*16) = rh[0];
            *reinterpret_cast<uint4*>(reinterpret_cast<char*>(Bs_lo) + bn0*(BSTR*2) + bq0*16) = rl[0];
            *reinterpret_cast<uint4*>(reinterpret_cast<char*>(Bs_hi) + bn1*(BSTR*2) + bq1*16) = rh[1];
            *reinterpret_cast<uint4*>(reinterpret_cast<char*>(Bs_lo) + bn1*(BSTR*2) + bq1*16) = rl[1];
            __syncthreads();

            // prefetch next (tap+1, or next unit's tap 0)
            {
                const bool wrap = (tap == 8);
                const bool valid = !wrap || (u + 1 < NU);
                if (valid) {
                    const int ro = wrap ? ROWOFF(u + 1 < NU ? u + 1 : u) : ROWOFF(u);
                    const int t1 = wrap ? 0 : (tap + 1)*64;
                    rh[0] = *(reinterpret_cast<const uint4*>(&g_Bw[0][ro + bn0][t1]) + bq0);
                    rl[0] = *(reinterpret_cast<const uint4*>(&g_Bw[1][ro + bn0][t1]) + bq0);
                    rh[1] = *(reinterpret_cast<const uint4*>(&g_Bw[0][ro + bn1][t1]) + bq1);
                    rl[1] = *(reinterpret_cast<const uint4*>(&g_Bw[1][ro + bn1][t1]) + bq1);
                }
            }

            const int tr = tap/3, tc = tap - tr*3;
            const int base_rc = tr*36 + tc + mt*16;
            const uint32_t a_off = (uint32_t)((base_rc + (lane & 15))*SLAB_STR*2)
                                 + ((lane >> 4) << 4);

            #pragma unroll
            for (int kq = 0; kq < 4; kq++) {
                unsigned ah[4], bh[4];
                ldsm_x4(ah, slab_hi_u + a_off + kq*32);
                ldsm_x4(bh, bs_hi_u + bfrag0 + kq*32);
                mma16816(acc[0], ah, bh[0], bh[1]);
                mma16816(acc[1], ah, bh[2], bh[3]);
                unsigned al[4];
                ldsm_x4(al, slab_lo_u + a_off + kq*32);
                mma16816(acc[0], al, bh[0], bh[1]);
                mma16816(acc[1], al, bh[2], bh[3]);
                unsigned bl[4];
                ldsm_x4(bl, bs_lo_u + bfrag0 + kq*32);
                mma16816(acc[0], ah, bl[0], bl[1]);
                mma16816(acc[1], ah, bl[2], bl[3]);
            }
        }

        // ---- Epilogue for unit u: thread owns 8 (px, oc) values ----
        #pragma unroll
        for (int nt = 0; nt < 2; nt++) {
            #pragma unroll
            for (int e = 0; e < 4; e++) {
                const int c  = mt*16 + (lane >> 2) + (e >> 1)*8;
                const int oc = nq*16 + nt*8 + (lane & 3)*2 + (e & 1);
                const int px = tile*IMW + c;
                float v = acc[nt][e];
                if (MODE == 0) {
                    size_t ib = (size_t)img*HD*HW + (size_t)oc*HW + px;
                    g_hode[ib] = g_h[ib] + tanhf(v + b_ode[oc])*dt;
                } else if (MODE == 1) {
                    float gx = g_gx[((size_t)(step*Bb + img)*(2*HD) + u*64 + oc)*HW + px];
                    float g = sigmoidf_(v + gx);
                    size_t ib = (size_t)img*HD*HW + (size_t)oc*HW + px;
                    if (u == 0) g_rh[ib] = g * g_hode[ib];
                    else        g_u[ib]  = g;
                } else if (MODE == 2) {
                    float cx = g_cx[((size_t)(step*Bb + img)*HD + oc)*HW + px];
                    size_t ib = (size_t)img*HD*HW + (size_t)oc*HW + px;
                    float ho = g_hode[ib];
                    g_h[ib] = ho + m*g_u[ib]*(tanhf(v + cx) - ho);
                } else {
                    if (u < 2)
                        g_gx[((size_t)img*(2*HD) + u*64 + oc)*HW + px] = v + b_gates[u*64 + oc];
                    else
                        g_cx[((size_t)img*HD + oc)*HW + px] = v + b_can[oc];
                }
            }
        }
    }
}

// ===========================================================================
// Head: z1 = relu(W1 h + b1); z2 = W2 z1 + b2; out = [z2[:64] ; |z2[64:]|]
// ===========================================================================
__global__ void __launch_bounds__(256) k_final(
    const float* __restrict__ w1, const float* __restrict__ b1,
    const float* __restrict__ w2, const float* __restrict__ b2,
    float* __restrict__ out)
{
    extern __shared__ float smemf[];
    float* w1s = smemf;          // [64][64]
    float* w2s = smemf + 4096;   // [128][64]
    const int tid = threadIdx.x, pb = blockIdx.x, b = blockIdx.y;
    for (int i = tid; i < 4096; i += 256) w1s[i] = w1[i];
    for (int i = tid; i < 8192; i += 256) w2s[i] = w2[i];
    __syncthreads();

    const int pix = pb*256 + tid;
    float z1[64];
    #pragma unroll
    for (int co = 0; co < 64; co++) z1[co] = b1[co];
    for (int ci = 0; ci < 64; ci++) {
        float hv = g_h[((size_t)b*HD + ci)*HW + pix];
        #pragma unroll
        for (int co = 0; co < 64; co++) z1[co] += w1s[co*64 + ci]*hv;
    }
    #pragma unroll
    for (int co = 0; co < 64; co++) z1[co] = fmaxf(z1[co], 0.f);

    for (int co2 = 0; co2 < 128; co2++) {
        float a = b2[co2];
        #pragma unroll
        for (int ci = 0; ci < 64; ci++) a += w2s[co2*64 + ci]*z1[ci];
        if (co2 < 64)
            out[((size_t)b*HD + co2)*HW + pix] = a;
        else
            out[(size_t)Bb*HD*HW + ((size_t)b*HD + (co2 - 64))*HW + pix] = fabsf(a);
    }
}

// ---------------------------------------------------------------------------
extern "C" void kernel_launch(void* const* d_in, const int* in_sizes, int n_in,
                              void* d_out, int out_size)
{
    const float* input   = (const float*)d_in[0];
    const float* ts      = (const float*)d_in[1];
    const float* mask    = (const float*)d_in[2];
    const float* w_gates = (const float*)d_in[3];
    const float* b_gates = (const float*)d_in[4];
    const float* w_can   = (const float*)d_in[5];
    const float* b_can   = (const float*)d_in[6];
    const float* w_ode   = (const float*)d_in[7];
    const float* b_ode   = (const float*)d_in[8];
    const float* w_t1    = (const float*)d_in[9];
    const float* b_t1    = (const float*)d_in[10];
    const float* w_t2    = (const float*)d_in[11];
    const float* b_t2    = (const float*)d_in[12];
    float* out = (float*)d_out;

    float* hptr;
    cudaGetSymbolAddress((void**)&hptr, g_h);

    cudaFuncSetAttribute(k_conv<0>, cudaFuncAttributeMaxDynamicSharedMemorySize, SMEMB);
    cudaFuncSetAttribute(k_conv<1>, cudaFuncAttributeMaxDynamicSharedMemorySize, SMEMB);
    cudaFuncSetAttribute(k_conv<2>, cudaFuncAttributeMaxDynamicSharedMemorySize, SMEMB);
    cudaFuncSetAttribute(k_conv<3>, cudaFuncAttributeMaxDynamicSharedMemorySize, SMEMB);

    cudaMemsetAsync(hptr, 0, (size_t)Bb*HD*HW*sizeof(float));
    k_wsplit<<<1008, 256>>>(w_ode, w_gates, w_can);

    // Precompute x-contributions for all T steps (fused: gx0, gx1, cx per CTA)
    k_conv<3><<<dim3(32, Tt*Bb), 256, SMEMB>>>(input, ts, mask, b_ode, b_gates, b_can, 0);

    // Sequential scan (gates fused: reset+update per CTA)
    for (int s = 0; s < Tt; s++) {
        k_conv<0><<<dim3(32, Bb), 256, SMEMB>>>(input, ts, mask, b_ode, b_gates, b_can, s);
        k_conv<1><<<dim3(32, Bb), 256, SMEMB>>>(input, ts, mask, b_ode, b_gates, b_can, s);
        k_conv<2><<<dim3(32, Bb), 256, SMEMB>>>(input, ts, mask, b_ode, b_gates, b_can, s);
    }

    k_final<<<dim3(4, Bb), 256, 12288*(int)sizeof(float)>>>(w_t1, b_t1, w_t2, b_t2, out);
}

// round 17
// speedup vs baseline: 1.2474x; 1.0959x over previous
#include <cuda_runtime.h>
#include <cuda_bf16.h>
#include <math.h>
#include <stdint.h>

// Problem constants
#define Bb 16
#define Tt 16
#define Cc 64
#define HD 64
#define HW 1024
#define IMW 32

// Scratch (device globals: no allocation allowed)
__device__ float g_h   [Bb*HD*HW];
__device__ float g_hode[Bb*HD*HW];
__device__ float g_rh  [Bb*HD*HW];
__device__ float g_u   [Bb*HD*HW];
__device__ float g_gx  [(size_t)Tt*Bb*2*HD*HW];   // x-part of gates conv (+bias)
__device__ float g_cx  [(size_t)Tt*Bb*HD*HW];     // x-part of cand conv (+bias)
// Pre-split weights, bf16 bits: [hl][row][k], k = tap*64 + ci
// rows: 0 ode | 64 gates_h(128) | 192 cand_h | 256 gates_x(128) | 384 cand_x
__device__ __align__(16) unsigned short g_Bw[2][448][576];

#define SLAB_STR 72
#define BSTR     72
#define BH       (64*BSTR)            // 4608 halves

// bf16 m16n8k16 MMA (standard PTX, sm_80+)
__device__ __forceinline__ void mma16816(float* c, const unsigned* a,
                                         unsigned b0, unsigned b1) {
    asm volatile(
        "mma.sync.aligned.m16n8k16.row.col.f32.bf16.bf16.f32 "
        "{%0,%1,%2,%3}, {%4,%5,%6,%7}, {%8,%9}, {%0,%1,%2,%3};\n"
        : "+f"(c[0]), "+f"(c[1]), "+f"(c[2]), "+f"(c[3])
        : "r"(a[0]), "r"(a[1]), "r"(a[2]), "r"(a[3]), "r"(b0), "r"(b1));
}
__device__ __forceinline__ void ldsm_x4(unsigned* r, uint32_t addr) {
    asm volatile("ldmatrix.sync.aligned.m8n8.x4.shared.b16 {%0,%1,%2,%3}, [%4];"
        : "=r"(r[0]), "=r"(r[1]), "=r"(r[2]), "=r"(r[3]) : "r"(addr));
}
__device__ __forceinline__ float sigmoidf_(float x) { return 1.f / (1.f + expf(-x)); }

// ===========================================================================
// Weight pre-split: fp32 -> bf16 hi/lo, layout [hl][row][tap*64+ci]
// ===========================================================================
__global__ void k_wsplit(const float* __restrict__ w_ode,
                         const float* __restrict__ w_gates,
                         const float* __restrict__ w_can)
{
    int idx = blockIdx.x*256 + threadIdx.x;     // 448*576 = 258048
    if (idx >= 448*576) return;
    int r = idx / 576, k = idx % 576;
    int tap = k >> 6, ci = k & 63;

    float v;
    if      (r < 64)  v = w_ode  [ r       *576  + ci*9      + tap];
    else if (r < 192) v = w_gates[(r-64)   *1152 + (64+ci)*9 + tap];
    else if (r < 256) v = w_can  [(r-192)  *1152 + (64+ci)*9 + tap];
    else if (r < 384) v = w_gates[(r-256)  *1152 + ci*9      + tap];
    else              v = w_can  [(r-384)  *1152 + ci*9      + tap];

    __nv_bfloat16 h = __float2bfloat16_rn(v);
    __nv_bfloat16 l = __float2bfloat16_rn(v - __bfloat162float(h));
    g_Bw[0][r][k] = __bfloat16_as_ushort(h);
    g_Bw[1][r][k] = __bfloat16_as_ushort(l);
}

// ===========================================================================
// Conv-as-GEMM with unit fusion. CTA (256 thr, 8 warps) owns MROWS image rows
// (MROWS*32 px) and runs NU sequential [Mpx x 64oc] conv-units on ONE slab.
// MODE: 0=ODE(1u,M32) 1=GATES(2u,M32) 2=CAND(1u,M32) 3=PRE(3u,M64: gx0,gx1,cx)
// grid = (32/MROWS tiles, nimg).
// Warp split: mt = w/NQW (m16 block), nq = w%NQW (oc block of 64/NQW).
//   scan: NQW=4 -> 2 m16 x 16oc, 2 acc chains
//   pre:  NQW=2 -> 4 m16 x 32oc, 4 acc chains, slab amortized over 2 rows
// ===========================================================================
template<int MODE>
__global__ void __launch_bounds__(256) k_conv(
    const float* __restrict__ x0, const float* __restrict__ ts,
    const float* __restrict__ mask, const float* __restrict__ b_ode,
    const float* __restrict__ b_gates, const float* __restrict__ b_can,
    int step)
{
    constexpr int NU     = (MODE == 1) ? 2 : (MODE == 3) ? 3 : 1;
    constexpr int MROWS  = (MODE == 3) ? 2 : 1;
    constexpr int NQW    = (MODE == 3) ? 2 : 4;   // warps along oc
    constexpr int NTILES = (64/NQW)/8;            // n8-tiles per warp (2 or 4)
    constexpr int SRC    = (MROWS + 2)*36;        // slab rc rows (108 or 144)
    constexpr int SLABH  = SRC*SLAB_STR;

    extern __shared__ unsigned short sm2[];
    unsigned short* slab_hi = sm2;
    unsigned short* slab_lo = sm2 + SLABH;
    unsigned short* Bs_hi   = sm2 + 2*SLABH;
    unsigned short* Bs_lo   = sm2 + 2*SLABH + BH;

    const int tid  = threadIdx.x;
    const int w    = tid >> 5, lane = tid & 31;
    const int mt   = w / NQW, nq = w % NQW;
    const int tile = blockIdx.x;
    const int img  = blockIdx.y;

    const float* in;
    if (MODE == 3) {
        int t = img >> 4, b = img & 15;
        in = x0 + ((size_t)(b*Tt + (Tt-1-t))*Cc)*HW;
    } else {
        in = (MODE == 0 ? g_h : (MODE == 1 ? g_hode : g_rh)) + (size_t)img*HD*HW;
    }

    auto ROWOFF = [](int u) {
        return (MODE == 0) ? 0
             : (MODE == 1) ? 64 + u*64
             : (MODE == 2) ? 192
             : (u == 2 ? 384 : 256 + u*64);
    };

    // ---- Build slabs (2 ci per 4B store): rows tile*MROWS-1 .. +MROWS ----
    for (int i = tid; i < 32*SRC; i += 256) {
        const int c2 = i / SRC;            // ci pair (ci = 2c2, 2c2+1)
        const int rc = i - c2*SRC;
        const int rr = rc / 36, cc = rc - rr*36;
        const int ir = tile*MROWS + rr - 1, ic = cc - 1;
        float va = 0.f, vb = 0.f;
        if ((unsigned)ir < 32u && (unsigned)ic < 32u) {
            const float* p = in + (2*c2)*HW + ir*IMW + ic;
            va = p[0];
            vb = p[HW];
        }
        __nv_bfloat162 h2 = __floats2bfloat162_rn(va, vb);
        __nv_bfloat162 l2 = __floats2bfloat162_rn(va - __bfloat162float(h2.x),
                                                  vb - __bfloat162float(h2.y));
        *reinterpret_cast<__nv_bfloat162*>(&slab_hi[rc*SLAB_STR + 2*c2]) = h2;
        *reinterpret_cast<__nv_bfloat162*>(&slab_lo[rc*SLAB_STR + 2*c2]) = l2;
    }

    const uint32_t slab_hi_u = (uint32_t)__cvta_generic_to_shared(slab_hi);
    const uint32_t slab_lo_u = (uint32_t)__cvta_generic_to_shared(slab_lo);
    const uint32_t bs_hi_u   = (uint32_t)__cvta_generic_to_shared(Bs_hi);
    const uint32_t bs_lo_u   = (uint32_t)__cvta_generic_to_shared(Bs_lo);

    // B fragment smem byte offset (warp's oc block = nq*(64/NQW))
    const uint32_t bfrag0 = (uint32_t)((nq*(64/NQW) + (lane & 7) + ((lane >> 4) << 3))*BSTR*2)
                          + (((lane >> 3) & 1) << 4);

    // warp's m position
    const int mrow = (MROWS == 2) ? (mt >> 1) : 0;   // image row within tile
    const int mcol = (MROWS == 2) ? (mt & 1) : mt;   // 16-px column block

    // B register prefetch: thread covers rows n = tid>>3 and (tid+256)>>3
    const int bn0 = tid >> 3,         bq0 = tid & 7;
    const int bn1 = (tid + 256) >> 3, bq1 = tid & 7;
    uint4 rh[2], rl[2];
    rh[0] = *(reinterpret_cast<const uint4*>(&g_Bw[0][ROWOFF(0) + bn0][0]) + bq0);
    rl[0] = *(reinterpret_cast<const uint4*>(&g_Bw[1][ROWOFF(0) + bn0][0]) + bq0);
    rh[1] = *(reinterpret_cast<const uint4*>(&g_Bw[0][ROWOFF(0) + bn1][0]) + bq1);
    rl[1] = *(reinterpret_cast<const uint4*>(&g_Bw[1][ROWOFF(0) + bn1][0]) + bq1);

    float dt = 0.f, m = 0.f;
    if (MODE == 0) dt = (step == 0) ? -0.01f : (ts[Tt-1-step] - ts[Tt-step]);
    if (MODE == 2) m  = mask[img*Tt + (Tt-1-step)];

    #pragma unroll
    for (int u = 0; u < NU; u++) {
        float acc[NTILES][4];
        #pragma unroll
        for (int nt = 0; nt < NTILES; nt++)
            #pragma unroll
            for (int e = 0; e < 4; e++) acc[nt][e] = 0.f;

        #pragma unroll 1
        for (int tap = 0; tap < 9; tap++) {
            __syncthreads();   // prior reads of Bs done (tap0/u0: slab stores issued)
            *reinterpret_cast<uint4*>(reinterpret_cast<char*>(Bs_hi) + bn0*(BSTR*2) + bq0*16) = rh[0];
            *reinterpret_cast<uint4*>(reinterpret_cast<char*>(Bs_lo) + bn0*(BSTR*2) + bq0*16) = rl[0];
            *reinterpret_cast<uint4*>(reinterpret_cast<char*>(Bs_hi) + bn1*(BSTR*2) + bq1*16) = rh[1];
            *reinterpret_cast<uint4*>(reinterpret_cast<char*>(Bs_lo) + bn1*(BSTR*2) + bq1*16) = rl[1];
            __syncthreads();

            // prefetch next (tap+1, or next unit's tap 0)
            {
                const bool wrap = (tap == 8);
                const bool valid = !wrap || (u + 1 < NU);
                if (valid) {
                    const int ro = wrap ? ROWOFF(u + 1 < NU ? u + 1 : u) : ROWOFF(u);
                    const int t1 = wrap ? 0 : (tap + 1)*64;
                    rh[0] = *(reinterpret_cast<const uint4*>(&g_Bw[0][ro + bn0][t1]) + bq0);
                    rl[0] = *(reinterpret_cast<const uint4*>(&g_Bw[1][ro + bn0][t1]) + bq0);
                    rh[1] = *(reinterpret_cast<const uint4*>(&g_Bw[0][ro + bn1][t1]) + bq1);
                    rl[1] = *(reinterpret_cast<const uint4*>(&g_Bw[1][ro + bn1][t1]) + bq1);
                }
            }

            const int tr = tap/3, tc = tap - tr*3;
            const int base_rc = (tr + mrow)*36 + tc + mcol*16;
            const uint32_t a_off = (uint32_t)((base_rc + (lane & 15))*SLAB_STR*2)
                                 + ((lane >> 4) << 4);

            #pragma unroll
            for (int kq = 0; kq < 4; kq++) {
                unsigned ah[4], al[4];
                ldsm_x4(ah, slab_hi_u + a_off + kq*32);
                ldsm_x4(al, slab_lo_u + a_off + kq*32);
                #pragma unroll
                for (int p = 0; p < NTILES/2; p++) {
                    unsigned bh[4], bl[4];
                    const uint32_t boff = bfrag0 + (uint32_t)(p*16*BSTR*2) + kq*32;
                    ldsm_x4(bh, bs_hi_u + boff);
                    mma16816(acc[2*p],   ah, bh[0], bh[1]);
                    mma16816(acc[2*p+1], ah, bh[2], bh[3]);
                    mma16816(acc[2*p],   al, bh[0], bh[1]);
                    mma16816(acc[2*p+1], al, bh[2], bh[3]);
                    ldsm_x4(bl, bs_lo_u + boff);
                    mma16816(acc[2*p],   ah, bl[0], bl[1]);
                    mma16816(acc[2*p+1], ah, bl[2], bl[3]);
                }
            }
        }

        // ---- Epilogue for unit u ----
        #pragma unroll
        for (int nt = 0; nt < NTILES; nt++) {
            #pragma unroll
            for (int e = 0; e < 4; e++) {
                const int c  = mcol*16 + (lane >> 2) + (e >> 1)*8;
                const int oc = nq*(64/NQW) + nt*8 + (lane & 3)*2 + (e & 1);
                const int px = (tile*MROWS + mrow)*IMW + c;
                float v = acc[nt][e];
                if (MODE == 0) {
                    size_t ib = (size_t)img*HD*HW + (size_t)oc*HW + px;
                    g_hode[ib] = g_h[ib] + tanhf(v + b_ode[oc])*dt;
                } else if (MODE == 1) {
                    float gx = g_gx[((size_t)(step*Bb + img)*(2*HD) + u*64 + oc)*HW + px];
                    float g = sigmoidf_(v + gx);
                    size_t ib = (size_t)img*HD*HW + (size_t)oc*HW + px;
                    if (u == 0) g_rh[ib] = g * g_hode[ib];
                    else        g_u[ib]  = g;
                } else if (MODE == 2) {
                    float cx = g_cx[((size_t)(step*Bb + img)*HD + oc)*HW + px];
                    size_t ib = (size_t)img*HD*HW + (size_t)oc*HW + px;
                    float ho = g_hode[ib];
                    g_h[ib] = ho + m*g_u[ib]*(tanhf(v + cx) - ho);
                } else {
                    if (u < 2)
                        g_gx[((size_t)img*(2*HD) + u*64 + oc)*HW + px] = v + b_gates[u*64 + oc];
                    else
                        g_cx[((size_t)img*HD + oc)*HW + px] = v + b_can[oc];
                }
            }
        }
    }
}

// ===========================================================================
// Head: z1 = relu(W1 h + b1); z2 = W2 z1 + b2; out = [z2[:64] ; |z2[64:]|]
// ===========================================================================
__global__ void __launch_bounds__(256) k_final(
    const float* __restrict__ w1, const float* __restrict__ b1,
    const float* __restrict__ w2, const float* __restrict__ b2,
    float* __restrict__ out)
{
    extern __shared__ float smemf[];
    float* w1s = smemf;          // [64][64]
    float* w2s = smemf + 4096;   // [128][64]
    const int tid = threadIdx.x, pb = blockIdx.x, b = blockIdx.y;
    for (int i = tid; i < 4096; i += 256) w1s[i] = w1[i];
    for (int i = tid; i < 8192; i += 256) w2s[i] = w2[i];
    __syncthreads();

    const int pix = pb*256 + tid;
    float z1[64];
    #pragma unroll
    for (int co = 0; co < 64; co++) z1[co] = b1[co];
    for (int ci = 0; ci < 64; ci++) {
        float hv = g_h[((size_t)b*HD + ci)*HW + pix];
        #pragma unroll
        for (int co = 0; co < 64; co++) z1[co] += w1s[co*64 + ci]*hv;
    }
    #pragma unroll
    for (int co = 0; co < 64; co++) z1[co] = fmaxf(z1[co], 0.f);

    for (int co2 = 0; co2 < 128; co2++) {
        float a = b2[co2];
        #pragma unroll
        for (int ci = 0; ci < 64; ci++) a += w2s[co2*64 + ci]*z1[ci];
        if (co2 < 64)
            out[((size_t)b*HD + co2)*HW + pix] = a;
        else
            out[(size_t)Bb*HD*HW + ((size_t)b*HD + (co2 - 64))*HW + pix] = fabsf(a);
    }
}

// ---------------------------------------------------------------------------
extern "C" void kernel_launch(void* const* d_in, const int* in_sizes, int n_in,
                              void* d_out, int out_size)
{
    const float* input   = (const float*)d_in[0];
    const float* ts      = (const float*)d_in[1];
    const float* mask    = (const float*)d_in[2];
    const float* w_gates = (const float*)d_in[3];
    const float* b_gates = (const float*)d_in[4];
    const float* w_can   = (const float*)d_in[5];
    const float* b_can   = (const float*)d_in[6];
    const float* w_ode   = (const float*)d_in[7];
    const float* b_ode   = (const float*)d_in[8];
    const float* w_t1    = (const float*)d_in[9];
    const float* b_t1    = (const float*)d_in[10];
    const float* w_t2    = (const float*)d_in[11];
    const float* b_t2    = (const float*)d_in[12];
    float* out = (float*)d_out;

    float* hptr;
    cudaGetSymbolAddress((void**)&hptr, g_h);

    const int SMEM_SCAN = (2*108*SLAB_STR + 2*BH)*2;   // 49536 B
    const int SMEM_PRE  = (2*144*SLAB_STR + 2*BH)*2;   // 59904 B

    cudaFuncSetAttribute(k_conv<0>, cudaFuncAttributeMaxDynamicSharedMemorySize, SMEM_SCAN);
    cudaFuncSetAttribute(k_conv<1>, cudaFuncAttributeMaxDynamicSharedMemorySize, SMEM_SCAN);
    cudaFuncSetAttribute(k_conv<2>, cudaFuncAttributeMaxDynamicSharedMemorySize, SMEM_SCAN);
    cudaFuncSetAttribute(k_conv<3>, cudaFuncAttributeMaxDynamicSharedMemorySize, SMEM_PRE);

    cudaMemsetAsync(hptr, 0, (size_t)Bb*HD*HW*sizeof(float));
    k_wsplit<<<1008, 256>>>(w_ode, w_gates, w_can);

    // Precompute x-contributions for all T steps (M=64 tiles, 3 units/CTA)
    k_conv<3><<<dim3(16, Tt*Bb), 256, SMEM_PRE>>>(input, ts, mask, b_ode, b_gates, b_can, 0);

    // Sequential scan
    for (int s = 0; s < Tt; s++) {
        k_conv<0><<<dim3(32, Bb), 256, SMEM_SCAN>>>(input, ts, mask, b_ode, b_gates, b_can, s);
        k_conv<1><<<dim3(32, Bb), 256, SMEM_SCAN>>>(input, ts, mask, b_ode, b_gates, b_can, s);
        k_conv<2><<<dim3(32, Bb), 256, SMEM_SCAN>>>(input, ts, mask, b_ode, b_gates, b_can, s);
    }

    k_final<<<dim3(4, Bb), 256, 12288*(int)sizeof(float)>>>(w_t1, b_t1, w_t2, b_t2, out);
}